// round 6
// baseline (speedup 1.0000x reference)
#include <cuda_runtime.h>
#include <math.h>
#include <stdint.h>

#define TT 4096
#define DD 2048
#define FFDIM 8192
#define EE 8

// ---------------- device scratch (static: no allocations allowed) ----------------
static __device__ float g_h[(size_t)TT * FFDIM];  // gathered gelu(x@W1) rows, 128 MB
static __device__ float g_w[TT];
static __device__ int   g_idx[TT];
static __device__ int   g_perm[TT];
static __device__ int   g_counts[EE];
static __device__ int   g_offs[EE + 1];
static __device__ int   g_cursor[EE];

// round-to-nearest tf32 (simulates tcgen05 kind::tf32 numerics exactly, fp32 accum)
__device__ __forceinline__ float tf32r(float x) {
    unsigned r;
    asm("cvt.rna.tf32.f32 %0, %1;" : "=r"(r) : "f"(x));
    return __uint_as_float(r);
}

__device__ __forceinline__ float gelu_exact(float v) {
    return 0.5f * v * (1.0f + erff(v * 0.70710678118654752440f));
}

// ---------------- init: zero per-expert counters ----------------
__global__ void k_init() {
    int i = threadIdx.x;
    if (i < EE) g_counts[i] = 0;
}

// ---------------- router: 1 warp per token ----------------
__global__ void k_router(const float* __restrict__ x, const float* __restrict__ Wr) {
    int warp = (blockIdx.x * blockDim.x + threadIdx.x) >> 5;
    int lane = threadIdx.x & 31;
    if (warp >= TT) return;
    const float* xr = x + (size_t)warp * DD;
    float acc[EE];
#pragma unroll
    for (int e = 0; e < EE; e++) acc[e] = 0.f;
    for (int i = lane; i < DD; i += 32) {
        float xv = xr[i];
#pragma unroll
        for (int e = 0; e < EE; e++) acc[e] = fmaf(xv, Wr[e * DD + i], acc[e]);
    }
#pragma unroll
    for (int e = 0; e < EE; e++) {
#pragma unroll
        for (int off = 16; off > 0; off >>= 1)
            acc[e] += __shfl_xor_sync(0xffffffffu, acc[e], off);
    }
    if (lane == 0) {
        int best = 0;
        float bm = acc[0];
#pragma unroll
        for (int e = 1; e < EE; e++)
            if (acc[e] > bm) { bm = acc[e]; best = e; }  // strict > : first-max, matches argmax
        float s = 0.f;
#pragma unroll
        for (int e = 0; e < EE; e++) s += expf(acc[e] - bm);
        g_idx[warp] = best;
        g_w[warp] = 1.f / s;  // max softmax prob
        atomicAdd(&g_counts[best], 1);
    }
}

// ---------------- exclusive scan over 8 counts ----------------
__global__ void k_scan() {
    if (threadIdx.x == 0) {
        int s = 0;
#pragma unroll
        for (int e = 0; e < EE; e++) {
            g_offs[e] = s;
            g_cursor[e] = s;
            s += g_counts[e];
        }
        g_offs[EE] = s;
    }
}

// ---------------- scatter token ids into per-expert buckets ----------------
__global__ void k_scatter() {
    int t = blockIdx.x * blockDim.x + threadIdx.x;
    if (t < TT) {
        int pos = atomicAdd(&g_cursor[g_idx[t]], 1);
        g_perm[pos] = t;
    }
}

// ---------------- grouped GEMM, 128x128x16 tiles, tf32-rounded operands ----------------
// MODE 1: C_h[segRow, n] = gelu( sum_k x[perm[row], k] * W1[e, k, n] )   (A gathered)
// MODE 2: out[tok, n]    = w[tok] * sum_k g_h[segRow, k] * W2[e, k, n]   (C scattered)
template <int KDIM, int NDIM, int MODE>
__global__ __launch_bounds__(256, 2) void k_gemm(const float* __restrict__ A,
                                                 const float* __restrict__ B,
                                                 float* __restrict__ C) {
    const int e = blockIdx.z;
    const int segOff = g_offs[e];
    const int cnt = g_offs[e + 1] - segOff;
    const int rowBase = blockIdx.y * 128;
    if (rowBase >= cnt) return;  // padded grid: empty tiles exit immediately
    const int colBase = blockIdx.x * 128;
    const int tid = threadIdx.x;

    const float* Aeff = (MODE == 1) ? A : (const float*)g_h;

    __shared__ float As[16][128];
    __shared__ float Bs[16][128];
    __shared__ int toks[128];
    __shared__ float wts[128];

    if (tid < 128) {
        int r = rowBase + tid;
        int tk = (r < cnt) ? g_perm[segOff + r] : -1;
        toks[tid] = tk;
        wts[tid] = (tk >= 0) ? g_w[tk] : 0.f;
    }
    __syncthreads();

    // A-load mapping: q in {tid, tid+256}; r = q>>2 in [0,128), kv = (q&3)*4
    const int ra0 = tid >> 2;
    const int ra1 = ra0 + 64;
    const int ka0 = (tid & 3) * 4;
    // B-load mapping: kk = q>>5, n = (q&31)*4
    const int kb0 = tid >> 5;
    const int kb1 = kb0 + 8;
    const int nb0 = (tid & 31) * 4;

    bool av0, av1;
    const float* aPtr0;
    const float* aPtr1;
    if (MODE == 1) {
        int t0 = toks[ra0], t1 = toks[ra1];
        av0 = (t0 >= 0);
        av1 = (t1 >= 0);
        aPtr0 = Aeff + (size_t)(av0 ? t0 : 0) * KDIM + ka0;
        aPtr1 = Aeff + (size_t)(av1 ? t1 : 0) * KDIM + ka0;
    } else {
        av0 = (rowBase + ra0) < cnt;
        av1 = (rowBase + ra1) < cnt;
        aPtr0 = Aeff + (size_t)(segOff + (av0 ? rowBase + ra0 : 0)) * KDIM + ka0;
        aPtr1 = Aeff + (size_t)(segOff + (av1 ? rowBase + ra1 : 0)) * KDIM + ka0;
    }
    const float* bPtr0 = B + ((size_t)e * KDIM + kb0) * NDIM + colBase + nb0;
    const float* bPtr1 = B + ((size_t)e * KDIM + kb1) * NDIM + colBase + nb0;

    float acc[8][8];
#pragma unroll
    for (int i = 0; i < 8; i++)
#pragma unroll
        for (int j = 0; j < 8; j++) acc[i][j] = 0.f;

    const int ty4 = (tid >> 4) * 4;
    const int tx4 = (tid & 15) * 4;

    const float4 z4 = make_float4(0.f, 0.f, 0.f, 0.f);
    float4 pa0 = av0 ? *(const float4*)aPtr0 : z4;
    float4 pa1 = av1 ? *(const float4*)aPtr1 : z4;
    float4 pb0 = *(const float4*)bPtr0;
    float4 pb1 = *(const float4*)bPtr1;

    int k0 = 0;
    while (true) {
        // stage prefetched tile into SMEM with tf32 rounding
        As[ka0 + 0][ra0] = tf32r(pa0.x);
        As[ka0 + 1][ra0] = tf32r(pa0.y);
        As[ka0 + 2][ra0] = tf32r(pa0.z);
        As[ka0 + 3][ra0] = tf32r(pa0.w);
        As[ka0 + 0][ra1] = tf32r(pa1.x);
        As[ka0 + 1][ra1] = tf32r(pa1.y);
        As[ka0 + 2][ra1] = tf32r(pa1.z);
        As[ka0 + 3][ra1] = tf32r(pa1.w);
        float4 qb0 = make_float4(tf32r(pb0.x), tf32r(pb0.y), tf32r(pb0.z), tf32r(pb0.w));
        float4 qb1 = make_float4(tf32r(pb1.x), tf32r(pb1.y), tf32r(pb1.z), tf32r(pb1.w));
        *(float4*)&Bs[kb0][nb0] = qb0;
        *(float4*)&Bs[kb1][nb0] = qb1;
        __syncthreads();

        const bool more = (k0 + 16) < KDIM;
        if (more) {
            pa0 = av0 ? *(const float4*)(aPtr0 + k0 + 16) : z4;
            pa1 = av1 ? *(const float4*)(aPtr1 + k0 + 16) : z4;
            pb0 = *(const float4*)(bPtr0 + (size_t)(k0 + 16) * NDIM);
            pb1 = *(const float4*)(bPtr1 + (size_t)(k0 + 16) * NDIM);
        }

#pragma unroll
        for (int kk = 0; kk < 16; kk++) {
            float a[8], b[8];
            *(float4*)(a + 0) = *(const float4*)&As[kk][ty4];
            *(float4*)(a + 4) = *(const float4*)&As[kk][ty4 + 64];
            *(float4*)(b + 0) = *(const float4*)&Bs[kk][tx4];
            *(float4*)(b + 4) = *(const float4*)&Bs[kk][tx4 + 64];
#pragma unroll
            for (int i = 0; i < 8; i++)
#pragma unroll
                for (int j = 0; j < 8; j++) acc[i][j] = fmaf(a[i], b[j], acc[i][j]);
        }

        if (!more) break;
        __syncthreads();
        k0 += 16;
    }

    // epilogue
#pragma unroll
    for (int i = 0; i < 8; i++) {
        const int r = (i < 4) ? (ty4 + i) : (64 + ty4 + i - 4);
        const int rg = rowBase + r;
        if (rg >= cnt) continue;
        if (MODE == 1) {
            float* out = g_h + (size_t)(segOff + rg) * NDIM + colBase;
            float4 v0, v1;
            v0.x = gelu_exact(acc[i][0]);
            v0.y = gelu_exact(acc[i][1]);
            v0.z = gelu_exact(acc[i][2]);
            v0.w = gelu_exact(acc[i][3]);
            v1.x = gelu_exact(acc[i][4]);
            v1.y = gelu_exact(acc[i][5]);
            v1.z = gelu_exact(acc[i][6]);
            v1.w = gelu_exact(acc[i][7]);
            *(float4*)(out + tx4) = v0;
            *(float4*)(out + 64 + tx4) = v1;
        } else {
            const int tk = toks[r];
            const float w = wts[r];
            float* out = C + (size_t)tk * NDIM + colBase;
            float4 v0, v1;
            v0.x = acc[i][0] * w;
            v0.y = acc[i][1] * w;
            v0.z = acc[i][2] * w;
            v0.w = acc[i][3] * w;
            v1.x = acc[i][4] * w;
            v1.y = acc[i][5] * w;
            v1.z = acc[i][6] * w;
            v1.w = acc[i][7] * w;
            *(float4*)(out + tx4) = v0;
            *(float4*)(out + 64 + tx4) = v1;
        }
    }
}

extern "C" void kernel_launch(void* const* d_in, const int* in_sizes, int n_in,
                              void* d_out, int out_size) {
    (void)in_sizes;
    (void)n_in;
    (void)out_size;
    const float* x  = (const float*)d_in[0];
    const float* Wr = (const float*)d_in[1];
    const float* W1 = (const float*)d_in[2];
    const float* W2 = (const float*)d_in[3];
    float* out = (float*)d_out;

    k_init<<<1, 32>>>();
    k_router<<<TT / 8, 256>>>(x, Wr);          // 8 warps/block, 1 warp per token
    k_scan<<<1, 32>>>();
    k_scatter<<<TT / 256, 256>>>();

    dim3 g1(FFDIM / 128, TT / 128, EE);        // 64 x 32 x 8 (worst-case rows; empty tiles exit)
    k_gemm<DD, FFDIM, 1><<<g1, 256>>>(x, W1, nullptr);

    dim3 g2(DD / 128, TT / 128, EE);           // 16 x 32 x 8
    k_gemm<FFDIM, DD, 2><<<g2, 256>>>(nullptr, W2, out);
}

// round 11
// speedup vs baseline: 2.9732x; 2.9732x over previous
#include <cuda_runtime.h>
#include <math.h>
#include <stdint.h>

#define TT 4096
#define DD 2048
#define FFDIM 8192
#define EE 8

// ---------------- device scratch (static: no allocations allowed) ----------------
static __device__ float g_h[(size_t)TT * FFDIM];  // gelu(x@W1) rows in permuted order, 128 MB
static __device__ float g_w[TT];
static __device__ int   g_idx[TT];
static __device__ int   g_perm[TT];
static __device__ int   g_counts[EE];
static __device__ int   g_offs[EE + 1];
static __device__ int   g_cursor[EE];

// ---------------- helpers ----------------
__device__ __forceinline__ float tf32r(float x) {
    unsigned r; asm("cvt.rna.tf32.f32 %0, %1;" : "=r"(r) : "f"(x));
    return __uint_as_float(r);
}
__device__ __forceinline__ float gelu_exact(float v) {
    return 0.5f * v * (1.0f + erff(v * 0.70710678118654752440f));
}
// m16n8k8 tf32 MMA, fp32 accumulate (sm_80+ PTX, no arch-suffix gating)
__device__ __forceinline__ void mma8(float& d0, float& d1, float& d2, float& d3,
                                     float a0, float a1, float a2, float a3,
                                     float b0, float b1) {
    asm volatile(
        "mma.sync.aligned.m16n8k8.row.col.f32.tf32.tf32.f32 "
        "{%0,%1,%2,%3}, {%4,%5,%6,%7}, {%8,%9}, {%0,%1,%2,%3};"
        : "+f"(d0), "+f"(d1), "+f"(d2), "+f"(d3)
        : "r"(__float_as_uint(a0)), "r"(__float_as_uint(a1)),
          "r"(__float_as_uint(a2)), "r"(__float_as_uint(a3)),
          "r"(__float_as_uint(b0)), "r"(__float_as_uint(b1)));
}

// SMEM layout (bytes, dynamic):
//   toks[128]  @ 0
//   wts[128]   @ 512
//   A buffers: 128 rows x 36 floats  (stride 36 -> frag LDS bank = 4g+tig, conflict-free)
//   B buffers: 32 rows  x 136 floats (stride 136 -> frag LDS bank = 8tig+g, conflict-free)
#define SA 36
#define SB 136
#define OFF_TOK 0
#define OFF_WT  512
#define OFF_A0  1024
#define OFF_B0  (OFF_A0 + 128 * SA * 4)          // 1024 + 18432 = 19456
#define OFF_A1  (OFF_B0 + 32 * SB * 4)           // + 17408 = 36864
#define OFF_B1  (OFF_A1 + 128 * SA * 4)          // 55296
#define SMEM_SZ (OFF_B1 + 32 * SB * 4)           // 72704

// ---------------- routing kernels ----------------
__global__ void k_init() {
    int i = threadIdx.x;
    if (i < EE) g_counts[i] = 0;
}

__global__ void k_router(const float* __restrict__ x, const float* __restrict__ Wr) {
    int warp = (blockIdx.x * blockDim.x + threadIdx.x) >> 5;
    int lane = threadIdx.x & 31;
    if (warp >= TT) return;
    const float* xr = x + (size_t)warp * DD;
    float acc[EE];
#pragma unroll
    for (int e = 0; e < EE; e++) acc[e] = 0.f;
    for (int i = lane; i < DD; i += 32) {
        float xv = xr[i];
#pragma unroll
        for (int e = 0; e < EE; e++) acc[e] = fmaf(xv, Wr[e * DD + i], acc[e]);
    }
#pragma unroll
    for (int e = 0; e < EE; e++) {
#pragma unroll
        for (int off = 16; off > 0; off >>= 1)
            acc[e] += __shfl_xor_sync(0xffffffffu, acc[e], off);
    }
    if (lane == 0) {
        int best = 0;
        float bm = acc[0];
#pragma unroll
        for (int e = 1; e < EE; e++)
            if (acc[e] > bm) { bm = acc[e]; best = e; }  // strict > : first-max = argmax
        float s = 0.f;
#pragma unroll
        for (int e = 0; e < EE; e++) s += expf(acc[e] - bm);
        g_idx[warp] = best;
        g_w[warp] = 1.f / s;  // max softmax prob
        atomicAdd(&g_counts[best], 1);
    }
}

__global__ void k_scan() {
    if (threadIdx.x == 0) {
        int s = 0;
#pragma unroll
        for (int e = 0; e < EE; e++) {
            g_offs[e] = s;
            g_cursor[e] = s;
            s += g_counts[e];
        }
        g_offs[EE] = s;
    }
}

__global__ void k_scatter() {
    int t = blockIdx.x * blockDim.x + threadIdx.x;
    if (t < TT) {
        int pos = atomicAdd(&g_cursor[g_idx[t]], 1);
        g_perm[pos] = t;
    }
}

// ---------------- tf32 mma.sync grouped GEMM ----------------
// CTA 128x128, K-chunk 32, 8 warps (2 m x 4 n), warp tile 64x32.
// MODE 1: g_h[segRow, n] = gelu( sum_k x[perm[row], k] * W1[e, k, n] )   (A gathered)
// MODE 2: out[tok, n]    = w[tok] * sum_k g_h[segRow, k] * W2[e, k, n]   (C scattered)
template <int KDIM, int NDIM, int MODE>
__global__ void __launch_bounds__(256) k_gemm(const float* __restrict__ A,
                                              const float* __restrict__ B,
                                              float* __restrict__ C) {
    extern __shared__ char sm[];
    const int e = blockIdx.z;
    const int segOff = g_offs[e];
    const int cnt = g_offs[e + 1] - segOff;
    const int rowBase = blockIdx.y * 128;
    if (rowBase >= cnt) return;  // padded grid: empty tiles exit immediately
    const int colBase = blockIdx.x * 128;
    const int tid = threadIdx.x;

    int* toks = (int*)(sm + OFF_TOK);
    float* wts = (float*)(sm + OFF_WT);
    if (tid < 128) {
        int r = rowBase + tid;
        int tk = (r < cnt) ? g_perm[segOff + r] : -1;
        toks[tid] = tk;
        wts[tid] = (tk >= 0) ? g_w[tk] : 0.f;
    }
    __syncthreads();

    // -------- gmem load mapping (per thread, 4 float4 each for A and B) --------
    // A: rows r0+32i, 16B at float-col (tid&7)*4
    const int r0 = tid >> 3;
    const int ca = (tid & 7) * 4;
    const float* Aeff = (MODE == 1) ? A : (const float*)g_h;
    const float* aP[4];
    bool av[4];
#pragma unroll
    for (int i = 0; i < 4; i++) {
        int r = r0 + 32 * i;
        if (MODE == 1) {
            int tk = toks[r];
            av[i] = (tk >= 0);
            aP[i] = Aeff + (size_t)(av[i] ? tk : 0) * KDIM + ca;
        } else {
            av[i] = (rowBase + r) < cnt;
            aP[i] = Aeff + (size_t)(segOff + (av[i] ? rowBase + r : 0)) * KDIM + ca;
        }
    }
    // B: k-rows kb+8i, 16B at n-col (tid&31)*4
    const int kb = tid >> 5;
    const int nb = (tid & 31) * 4;
    const float* bP = B + ((size_t)e * KDIM + kb) * NDIM + colBase + nb;

    const float4 z4 = make_float4(0.f, 0.f, 0.f, 0.f);
    float4 pa[4], pb[4];
#pragma unroll
    for (int i = 0; i < 4; i++) pa[i] = av[i] ? *(const float4*)aP[i] : z4;
#pragma unroll
    for (int i = 0; i < 4; i++) pb[i] = *(const float4*)(bP + (size_t)(8 * i) * NDIM);

    // -------- warp/fragment mapping --------
    const int w = tid >> 5;
    const int lane = tid & 31;
    const int g = lane >> 2;       // groupID
    const int tg = lane & 3;       // threadID_in_group
    const int wm = (w & 1) * 64;   // warp m-offset
    const int wn = (w >> 1) * 32;  // warp n-offset

    float acc[4][4][4];
#pragma unroll
    for (int i = 0; i < 4; i++)
#pragma unroll
        for (int j = 0; j < 4; j++)
#pragma unroll
            for (int q = 0; q < 4; q++) acc[i][j][q] = 0.f;

    const int NC = KDIM / 32;
    for (int it = 0; it < NC; ++it) {
        float* As = (float*)(sm + ((it & 1) ? OFF_A1 : OFF_A0));
        float* Bs = (float*)(sm + ((it & 1) ? OFF_B1 : OFF_B0));

        // stage current chunk (tf32-rounded). STS.128, conflict-free per phase.
#pragma unroll
        for (int i = 0; i < 4; i++) {
            float4 q = make_float4(tf32r(pa[i].x), tf32r(pa[i].y), tf32r(pa[i].z), tf32r(pa[i].w));
            *(float4*)(As + (r0 + 32 * i) * SA + ca) = q;
        }
#pragma unroll
        for (int i = 0; i < 4; i++) {
            float4 q = make_float4(tf32r(pb[i].x), tf32r(pb[i].y), tf32r(pb[i].z), tf32r(pb[i].w));
            *(float4*)(Bs + (kb + 8 * i) * SB + nb) = q;
        }
        __syncthreads();

        // prefetch next chunk (overlaps MMA block below)
        if (it + 1 < NC) {
            size_t k0 = (size_t)(it + 1) * 32;
#pragma unroll
            for (int i = 0; i < 4; i++) pa[i] = av[i] ? *(const float4*)(aP[i] + k0) : z4;
            const float* bpk = bP + k0 * NDIM;
#pragma unroll
            for (int i = 0; i < 4; i++) pb[i] = *(const float4*)(bpk + (size_t)(8 * i) * NDIM);
        }

        // 4 k-steps of 8
#pragma unroll
        for (int kk = 0; kk < 4; kk++) {
            const int k8 = kk * 8;
            float fa[4][4], fb[4][2];
#pragma unroll
            for (int i = 0; i < 4; i++) {
                const int row = wm + i * 16 + g;
                fa[i][0] = As[row * SA + k8 + tg];
                fa[i][1] = As[(row + 8) * SA + k8 + tg];
                fa[i][2] = As[row * SA + k8 + tg + 4];
                fa[i][3] = As[(row + 8) * SA + k8 + tg + 4];
            }
#pragma unroll
            for (int j = 0; j < 4; j++) {
                const int n = wn + j * 8 + g;
                fb[j][0] = Bs[(k8 + tg) * SB + n];
                fb[j][1] = Bs[(k8 + tg + 4) * SB + n];
            }
#pragma unroll
            for (int i = 0; i < 4; i++)
#pragma unroll
                for (int j = 0; j < 4; j++)
                    mma8(acc[i][j][0], acc[i][j][1], acc[i][j][2], acc[i][j][3],
                         fa[i][0], fa[i][1], fa[i][2], fa[i][3], fb[j][0], fb[j][1]);
        }
        __syncthreads();
    }

    // -------- epilogue: regs -> gmem (float2 stores) --------
#pragma unroll
    for (int i = 0; i < 4; i++) {
#pragma unroll
        for (int h = 0; h < 2; h++) {
            const int rl = wm + i * 16 + g + 8 * h;  // local row
            const int rg = rowBase + rl;
            if (rg >= cnt) continue;
            float* out;
            if (MODE == 1) {
                out = g_h + (size_t)(segOff + rg) * NDIM + colBase;
            } else {
                out = C + (size_t)toks[rl] * NDIM + colBase;
            }
            const float wv = wts[rl];
#pragma unroll
            for (int j = 0; j < 4; j++) {
                const int col = wn + j * 8 + 2 * tg;
                float2 v;
                if (MODE == 1) {
                    v.x = gelu_exact(acc[i][j][2 * h]);
                    v.y = gelu_exact(acc[i][j][2 * h + 1]);
                } else {
                    v.x = acc[i][j][2 * h] * wv;
                    v.y = acc[i][j][2 * h + 1] * wv;
                }
                *(float2*)(out + col) = v;
            }
        }
    }
}

extern "C" void kernel_launch(void* const* d_in, const int* in_sizes, int n_in,
                              void* d_out, int out_size) {
    (void)in_sizes;
    (void)n_in;
    (void)out_size;
    const float* x  = (const float*)d_in[0];
    const float* Wr = (const float*)d_in[1];
    const float* W1 = (const float*)d_in[2];
    const float* W2 = (const float*)d_in[3];
    float* out = (float*)d_out;

    cudaFuncSetAttribute(k_gemm<DD, FFDIM, 1>,
                         cudaFuncAttributeMaxDynamicSharedMemorySize, SMEM_SZ);
    cudaFuncSetAttribute(k_gemm<FFDIM, DD, 2>,
                         cudaFuncAttributeMaxDynamicSharedMemorySize, SMEM_SZ);

    k_init<<<1, 32>>>();
    k_router<<<TT / 8, 256>>>(x, Wr);
    k_scan<<<1, 32>>>();
    k_scatter<<<TT / 256, 256>>>();

    dim3 g1(FFDIM / 128, TT / 128, EE);  // 64 x 32 x 8 (empty padded tiles exit)
    k_gemm<DD, FFDIM, 1><<<g1, 256, SMEM_SZ>>>(x, W1, nullptr);

    dim3 g2(DD / 128, TT / 128, EE);     // 16 x 32 x 8
    k_gemm<FFDIM, DD, 2><<<g2, 256, SMEM_SZ>>>(nullptr, W2, out);
}

// round 12
// speedup vs baseline: 3.4735x; 1.1682x over previous
#include <cuda_runtime.h>
#include <math.h>
#include <stdint.h>

#define TT 4096
#define DD 2048
#define FFDIM 8192
#define EE 8

// ---------------- device scratch (static: no allocations allowed) ----------------
static __device__ float g_h[(size_t)TT * FFDIM];   // tf32-rounded gelu(x@W1), permuted rows
static __device__ float g_xr[(size_t)TT * DD];     // tf32-rounded x
static __device__ float g_w[TT];
static __device__ int   g_idx[TT];
static __device__ int   g_perm[TT];
static __device__ int   g_counts[EE];
static __device__ int   g_offs[EE + 1];
static __device__ int   g_cursor[EE];

// ---------------- helpers ----------------
__device__ __forceinline__ float tf32r(float x) {
    unsigned r; asm("cvt.rna.tf32.f32 %0, %1;" : "=r"(r) : "f"(x));
    return __uint_as_float(r);
}
__device__ __forceinline__ float gelu_exact(float v) {
    return 0.5f * v * (1.0f + erff(v * 0.70710678118654752440f));
}
__device__ __forceinline__ void mma8(float& d0, float& d1, float& d2, float& d3,
                                     float a0, float a1, float a2, float a3,
                                     float b0, float b1) {
    asm volatile(
        "mma.sync.aligned.m16n8k8.row.col.f32.tf32.tf32.f32 "
        "{%0,%1,%2,%3}, {%4,%5,%6,%7}, {%8,%9}, {%0,%1,%2,%3};"
        : "+f"(d0), "+f"(d1), "+f"(d2), "+f"(d3)
        : "r"(__float_as_uint(a0)), "r"(__float_as_uint(a1)),
          "r"(__float_as_uint(a2)), "r"(__float_as_uint(a3)),
          "r"(__float_as_uint(b0)), "r"(__float_as_uint(b1)));
}
__device__ __forceinline__ uint32_t smem_u32(const void* p) {
    uint32_t a;
    asm("{ .reg .u64 t; cvta.to.shared.u64 t, %1; cvt.u32.u64 %0, t; }" : "=r"(a) : "l"(p));
    return a;
}
#define CPA16(dst, src) \
    asm volatile("cp.async.cg.shared.global [%0], [%1], 16;" :: "r"(dst), "l"(src))
#define CPA_COMMIT() asm volatile("cp.async.commit_group;" ::: "memory")
#define CPA_WAIT1() asm volatile("cp.async.wait_group 1;" ::: "memory")
#define CPA_WAIT0() asm volatile("cp.async.wait_group 0;" ::: "memory")

// SMEM layout (dynamic):
//   toks[128] @0, wts[128] @512
//   3 stages @1024: per stage A(128r x 36f pad, 18432B) then B(32k x 136f pad, 17408B)
#define SA 36
#define SB 136
#define ASZ (128 * SA * 4)   // 18432
#define BSZ (32 * SB * 4)    // 17408
#define STAGE (ASZ + BSZ)    // 35840
#define OFF_STG 1024
#define SMEM_SZ (OFF_STG + 3 * STAGE)  // 108544 -> 2 CTAs/SM = 217088 <= 227KB

// ---------------- routing kernels ----------------
__global__ void k_init() {
    int i = threadIdx.x;
    if (i < EE) g_counts[i] = 0;
}

__global__ void k_router(const float* __restrict__ x, const float* __restrict__ Wr) {
    int warp = (blockIdx.x * blockDim.x + threadIdx.x) >> 5;
    int lane = threadIdx.x & 31;
    if (warp >= TT) return;
    const float* xr = x + (size_t)warp * DD;
    float acc[EE];
#pragma unroll
    for (int e = 0; e < EE; e++) acc[e] = 0.f;
    for (int i = lane; i < DD; i += 32) {
        float xv = xr[i];
#pragma unroll
        for (int e = 0; e < EE; e++) acc[e] = fmaf(xv, Wr[e * DD + i], acc[e]);
    }
#pragma unroll
    for (int e = 0; e < EE; e++) {
#pragma unroll
        for (int off = 16; off > 0; off >>= 1)
            acc[e] += __shfl_xor_sync(0xffffffffu, acc[e], off);
    }
    if (lane == 0) {
        int best = 0;
        float bm = acc[0];
#pragma unroll
        for (int e = 1; e < EE; e++)
            if (acc[e] > bm) { bm = acc[e]; best = e; }  // strict > : first-max = argmax
        float s = 0.f;
#pragma unroll
        for (int e = 0; e < EE; e++) s += expf(acc[e] - bm);
        g_idx[warp] = best;
        g_w[warp] = 1.f / s;  // max softmax prob
        atomicAdd(&g_counts[best], 1);
    }
}

__global__ void k_scan() {
    if (threadIdx.x == 0) {
        int s = 0;
#pragma unroll
        for (int e = 0; e < EE; e++) {
            g_offs[e] = s;
            g_cursor[e] = s;
            s += g_counts[e];
        }
        g_offs[EE] = s;
    }
}

__global__ void k_scatter() {
    int t = blockIdx.x * blockDim.x + threadIdx.x;
    if (t < TT) {
        int pos = atomicAdd(&g_cursor[g_idx[t]], 1);
        g_perm[pos] = t;
    }
}

// pre-round x to tf32 once (A operand of GEMM1 then needs no cvt in the mainloop)
__global__ void k_roundx(const float4* __restrict__ x, float4* __restrict__ xr) {
    size_t i = (size_t)blockIdx.x * blockDim.x + threadIdx.x;  // 2M float4
    float4 v = x[i];
    v.x = tf32r(v.x); v.y = tf32r(v.y); v.z = tf32r(v.z); v.w = tf32r(v.w);
    xr[i] = v;
}

// ---------------- tf32 mma.sync grouped GEMM ----------------
// CTA 128x128, K-chunk 32, 4 warps (2m x 2n), warp tile 64x64.
// 3-stage cp.async pipeline, one __syncthreads per chunk.
// MODE 1: g_h[segRow, n] = tf32r(gelu( sum_k xr[perm[row], k] * W1[e, k, n] ))
// MODE 2: out[tok, n]    = w[tok] * sum_k g_h[segRow, k] * W2[e, k, n]
template <int KDIM, int NDIM, int MODE>
__global__ void __launch_bounds__(128, 2) k_gemm(const float* __restrict__ A,
                                                 const float* __restrict__ B,
                                                 float* __restrict__ C) {
    extern __shared__ char sm[];
    const int e = blockIdx.z;
    const int segOff = g_offs[e];
    const int cnt = g_offs[e + 1] - segOff;
    const int rowBase = blockIdx.y * 128;
    if (rowBase >= cnt) return;  // padded grid: empty tiles exit immediately
    const int colBase = blockIdx.x * 128;
    const int tid = threadIdx.x;

    int* toks = (int*)sm;
    float* wts = (float*)(sm + 512);
    {
        int r = rowBase + tid;
        int tk = (r < cnt) ? g_perm[segOff + r] : -1;
        toks[tid] = tk;
        wts[tid] = (tk >= 0) ? g_w[tk] : 0.f;
    }
    __syncthreads();

    const uint32_t sbase = smem_u32(sm);
    const float* Aeff = (MODE == 1) ? A : (const float*)g_h;

    // ---- cp.async assignments ----
    // A: thread covers rows rb+16i (i=0..7), 16B chunk ca of the 128B k-row slice
    const int rb = tid >> 3;       // 0..15
    const int ca = tid & 7;        // 0..7
    // B: thread covers k-row kb, chunks (cb + 4i) (i=0..7) of the 512B n-row
    const int kb = tid >> 2;       // 0..31
    const int cb = tid & 3;        // 0..3

    const float* aSrc[8];
#pragma unroll
    for (int i = 0; i < 8; i++) {
        int r = rb + 16 * i;
        if (MODE == 1) {
            int tk = toks[r];
            aSrc[i] = Aeff + (size_t)(tk >= 0 ? tk : 0) * KDIM + ca * 4;
        } else {
            int rr = (rowBase + r < cnt) ? r : 0;
            aSrc[i] = Aeff + (size_t)(segOff + rowBase + rr) * KDIM + ca * 4;
        }
    }
    const float* bP = B + ((size_t)e * KDIM + kb) * NDIM + colBase;

    const uint32_t dA0 = sbase + OFF_STG + (uint32_t)(rb * SA + ca * 4) * 4;
    const uint32_t dB0 = sbase + OFF_STG + ASZ + (uint32_t)(kb * SB) * 4;

    // ---- issue one stage ----
    auto issue = [&](int stage, int k0) {
        uint32_t da = dA0 + stage * STAGE;
        uint32_t db = dB0 + stage * STAGE;
        const float* bs = bP + (size_t)k0 * NDIM;
#pragma unroll
        for (int i = 0; i < 8; i++) CPA16(da + i * (16 * SA * 4), aSrc[i] + k0);
#pragma unroll
        for (int i = 0; i < 8; i++) CPA16(db + (cb + 4 * i) * 16, bs + (cb + 4 * i) * 4);
        CPA_COMMIT();
    };

    // ---- fragment mapping: 4 warps, 2m x 2n, warp tile 64x64 ----
    const int w = tid >> 5;
    const int lane = tid & 31;
    const int g = lane >> 2;
    const int tg = lane & 3;
    const int wm = (w & 1) * 64;
    const int wn = (w >> 1) * 64;

    float acc[4][8][4];
#pragma unroll
    for (int i = 0; i < 4; i++)
#pragma unroll
        for (int j = 0; j < 8; j++)
#pragma unroll
            for (int q = 0; q < 4; q++) acc[i][j][q] = 0.f;

    const int NC = KDIM / 32;
    issue(0, 0);
    issue(1, 32);

    for (int it = 0; it < NC; ++it) {
        if (it + 1 < NC) { CPA_WAIT1(); } else { CPA_WAIT0(); }
        __syncthreads();
        if (it + 2 < NC) issue((it + 2) % 3, (it + 2) * 32);

        const float* As = (const float*)(sm + OFF_STG + (it % 3) * STAGE);
        const float* Bs = (const float*)(sm + OFF_STG + (it % 3) * STAGE + ASZ);

#pragma unroll
        for (int kk = 0; kk < 4; kk++) {
            const int k8 = kk * 8;
            float fa[4][4], fb[8][2];
#pragma unroll
            for (int i = 0; i < 4; i++) {
                const int row = wm + i * 16 + g;
                fa[i][0] = As[row * SA + k8 + tg];
                fa[i][1] = As[(row + 8) * SA + k8 + tg];
                fa[i][2] = As[row * SA + k8 + tg + 4];
                fa[i][3] = As[(row + 8) * SA + k8 + tg + 4];
            }
#pragma unroll
            for (int j = 0; j < 8; j++) {
                const int n = wn + j * 8 + g;
                fb[j][0] = tf32r(Bs[(k8 + tg) * SB + n]);
                fb[j][1] = tf32r(Bs[(k8 + tg + 4) * SB + n]);
            }
#pragma unroll
            for (int i = 0; i < 4; i++)
#pragma unroll
                for (int j = 0; j < 8; j++)
                    mma8(acc[i][j][0], acc[i][j][1], acc[i][j][2], acc[i][j][3],
                         fa[i][0], fa[i][1], fa[i][2], fa[i][3], fb[j][0], fb[j][1]);
        }
    }

    // ---- epilogue: regs -> gmem (float2) ----
#pragma unroll
    for (int i = 0; i < 4; i++) {
#pragma unroll
        for (int h = 0; h < 2; h++) {
            const int rl = wm + i * 16 + g + 8 * h;
            const int rg = rowBase + rl;
            if (rg >= cnt) continue;
            float* out;
            if (MODE == 1) {
                out = g_h + (size_t)(segOff + rg) * NDIM + colBase;
            } else {
                out = C + (size_t)toks[rl] * NDIM + colBase;
            }
            const float wv = wts[rl];
#pragma unroll
            for (int j = 0; j < 8; j++) {
                const int col = wn + j * 8 + 2 * tg;
                float2 v;
                if (MODE == 1) {
                    v.x = tf32r(gelu_exact(acc[i][j][2 * h]));      // pre-round h for GEMM2
                    v.y = tf32r(gelu_exact(acc[i][j][2 * h + 1]));
                } else {
                    v.x = acc[i][j][2 * h] * wv;
                    v.y = acc[i][j][2 * h + 1] * wv;
                }
                *(float2*)(out + col) = v;
            }
        }
    }
}

extern "C" void kernel_launch(void* const* d_in, const int* in_sizes, int n_in,
                              void* d_out, int out_size) {
    (void)in_sizes;
    (void)n_in;
    (void)out_size;
    const float* x  = (const float*)d_in[0];
    const float* Wr = (const float*)d_in[1];
    const float* W1 = (const float*)d_in[2];
    const float* W2 = (const float*)d_in[3];
    float* out = (float*)d_out;

    cudaFuncSetAttribute(k_gemm<DD, FFDIM, 1>,
                         cudaFuncAttributeMaxDynamicSharedMemorySize, SMEM_SZ);
    cudaFuncSetAttribute(k_gemm<FFDIM, DD, 2>,
                         cudaFuncAttributeMaxDynamicSharedMemorySize, SMEM_SZ);

    k_init<<<1, 32>>>();
    k_router<<<TT / 8, 256>>>(x, Wr);
    k_scan<<<1, 32>>>();
    k_scatter<<<TT / 256, 256>>>();

    float* xr;
    cudaGetSymbolAddress((void**)&xr, g_xr);
    k_roundx<<<(TT * DD / 4) / 256, 256>>>((const float4*)x, (float4*)xr);

    dim3 g1(FFDIM / 128, TT / 128, EE);  // 64 x 32 x 8 (empty padded tiles exit)
    k_gemm<DD, FFDIM, 1><<<g1, 128, SMEM_SZ>>>(xr, W1, nullptr);

    dim3 g2(DD / 128, TT / 128, EE);     // 16 x 32 x 8
    k_gemm<FFDIM, DD, 2><<<g2, 128, SMEM_SZ>>>(nullptr, W2, out);
}